// round 2
// baseline (speedup 1.0000x reference)
#include <cuda_runtime.h>
#include <cuda_bf16.h>
#include <math.h>

#define NN   50000
#define FIN  256
#define HID  64
#define CC   40
#define EE   1600000

#define NC        (NN*CC)            // 2,000,000
#define OFF_LOGSM 0
#define OFF_XOUT  (NC)               // 2,000,000
#define OFF_COS   (2*NC)             // 4,000,000
#define OFF_GNN   (2*NC + EE)        // 5,600,000
#define OFF_SM    (2*NC + 2*EE)      // 7,200,000

// ---------------- device scratch (no allocations allowed) ----------------
__device__ float g_xw[NN*HID];     // xw = x@W1 ; later reused as hw = h@W2 ([N,40])
__device__ float g_hacc[NN*HID];   // layer-1 accumulator, becomes h after relu+bias
__device__ float g_oacc[NN*CC];    // layer-2 accumulator, becomes x_out
__device__ float g_dinv[NN];       // deg -> rsqrt(deg)
__device__ float g_rn[NN];         // 1/max(||x_out||, eps)
__device__ int   g_src[EE];
__device__ int   g_dst[EE];
__device__ float g_norm[EE];
__device__ int   g_flag;           // 1 if edge_index is int64

__device__ __forceinline__ void red_add_v4(float* p, float4 v) {
    asm volatile("red.global.add.v4.f32 [%0], {%1,%2,%3,%4};"
                 :: "l"(p), "f"(v.x), "f"(v.y), "f"(v.z), "f"(v.w) : "memory");
}

// ---------------- dtype detect + edge normalize ----------------
__global__ void k_detect(const unsigned* __restrict__ p) {
    int lane = threadIdx.x;
    bool odd_nonzero = false;
    for (int k = lane; k < 4096; k += 32)
        if (p[2*k + 1] != 0u) odd_nonzero = true;
    odd_nonzero = __any_sync(0xffffffffu, odd_nonzero);
    if (lane == 0) g_flag = odd_nonzero ? 0 : 1;   // all-high-words-zero => int64
}

__global__ void k_convert(const void* __restrict__ p) {
    int e = blockIdx.x * blockDim.x + threadIdx.x;
    if (e >= EE) return;
    if (g_flag) {
        const long long* q = (const long long*)p;
        g_src[e] = (int)q[e];
        g_dst[e] = (int)q[e + EE];
    } else {
        const int* q = (const int*)p;
        g_src[e] = q[e];
        g_dst[e] = q[e + EE];
    }
}

// ---------------- degree / dinv / per-edge norm ----------------
__global__ void k_deg_init() {
    int i = blockIdx.x * blockDim.x + threadIdx.x;
    if (i < NN) g_dinv[i] = 1.0f;   // self-loop contributes 1
}
__global__ void k_deg_acc() {
    int e = blockIdx.x * blockDim.x + threadIdx.x;
    if (e < EE) atomicAdd(&g_dinv[g_dst[e]], 1.0f);
}
__global__ void k_dinv() {
    int i = blockIdx.x * blockDim.x + threadIdx.x;
    if (i < NN) g_dinv[i] = rsqrtf(g_dinv[i]);
}
__global__ void k_norm() {
    int e = blockIdx.x * blockDim.x + threadIdx.x;
    if (e < EE) g_norm[e] = g_dinv[g_src[e]] * g_dinv[g_dst[e]];
}

// ---------------- GEMM1: xw[N,64] = x[N,256] @ W1[256,64] ----------------
__global__ void k_gemm1(const float* __restrict__ x, const float* __restrict__ W) {
    __shared__ float Xs[64][65];
    __shared__ float Ws[64][68];
    int t = threadIdx.x;                 // 256 threads
    int rowBase = blockIdx.x * 64;
    int tx = t & 15, ty = t >> 4;
    float acc[4][4] = {};
    for (int kb = 0; kb < 4; kb++) {
        #pragma unroll
        for (int l = 0; l < 16; l++) {
            int lin = t + l * 256;
            int r = lin >> 6, k = lin & 63;
            int gr = rowBase + r;
            Xs[r][k] = (gr < NN) ? x[gr * FIN + kb * 64 + k] : 0.0f;
            Ws[r][k] = W[(kb * 64 + r) * HID + k];
        }
        __syncthreads();
        #pragma unroll
        for (int kk = 0; kk < 64; kk++) {
            float a[4], b[4];
            #pragma unroll
            for (int i = 0; i < 4; i++) a[i] = Xs[ty * 4 + i][kk];
            #pragma unroll
            for (int j = 0; j < 4; j++) b[j] = Ws[kk][tx * 4 + j];
            #pragma unroll
            for (int i = 0; i < 4; i++)
                #pragma unroll
                for (int j = 0; j < 4; j++) acc[i][j] += a[i] * b[j];
        }
        __syncthreads();
    }
    #pragma unroll
    for (int i = 0; i < 4; i++) {
        int gr = rowBase + ty * 4 + i;
        if (gr < NN) {
            #pragma unroll
            for (int j = 0; j < 4; j++) g_xw[gr * HID + tx * 4 + j] = acc[i][j];
        }
    }
}

// ---------------- layer-1 self-loop init + scatter + relu ----------------
__global__ void k_init1() {
    int tid = blockIdx.x * blockDim.x + threadIdx.x;     // N*16
    if (tid >= NN * 16) return;
    int i = tid >> 4;
    float di = g_dinv[i]; float s = di * di;
    float4 v = ((const float4*)g_xw)[tid];
    v.x *= s; v.y *= s; v.z *= s; v.w *= s;
    ((float4*)g_hacc)[tid] = v;
}
__global__ void k_scatter1() {
    long long tid = (long long)blockIdx.x * blockDim.x + threadIdx.x;  // E*16
    if (tid >= (long long)EE * 16) return;
    int e = (int)(tid >> 4), c = (int)(tid & 15);
    int s = g_src[e], d = g_dst[e];
    float nrm = g_norm[e];
    float4 v = ((const float4*)g_xw)[s * 16 + c];
    v.x *= nrm; v.y *= nrm; v.z *= nrm; v.w *= nrm;
    red_add_v4(g_hacc + d * HID + c * 4, v);
}
__global__ void k_relu(const float* __restrict__ b1) {
    int tid = blockIdx.x * blockDim.x + threadIdx.x;     // N*16
    if (tid >= NN * 16) return;
    int c = tid & 15;
    float4 b = ((const float4*)b1)[c];
    float4 v = ((const float4*)g_hacc)[tid];
    v.x = fmaxf(v.x + b.x, 0.f); v.y = fmaxf(v.y + b.y, 0.f);
    v.z = fmaxf(v.z + b.z, 0.f); v.w = fmaxf(v.w + b.w, 0.f);
    ((float4*)g_hacc)[tid] = v;
}

// ---------------- GEMM2: hw[N,40] = h[N,64] @ W2[64,40] (into g_xw) ------
__global__ void k_gemm2(const float* __restrict__ W2) {
    __shared__ float Ws[HID * CC];      // 2560 floats
    int t = threadIdx.x;                // 256
    #pragma unroll
    for (int l = 0; l < 10; l++) Ws[t + l * 256] = W2[t + l * 256];
    __syncthreads();
    int gid = blockIdx.x * 256 + t;
    if (gid >= NN * CC) return;
    int i = gid / CC, c = gid - i * CC;
    const float* h = g_hacc + i * HID;
    float acc = 0.f;
    #pragma unroll
    for (int k = 0; k < HID; k++) acc += h[k] * Ws[k * CC + c];
    g_xw[gid] = acc;
}

// ---------------- layer-2 self-loop init + scatter ----------------
__global__ void k_init2() {
    int tid = blockIdx.x * blockDim.x + threadIdx.x;     // N*10
    if (tid >= NN * 10) return;
    int i = tid / 10;
    float di = g_dinv[i]; float s = di * di;
    float4 v = ((const float4*)g_xw)[tid];
    v.x *= s; v.y *= s; v.z *= s; v.w *= s;
    ((float4*)g_oacc)[tid] = v;
}
__global__ void k_scatter2() {
    long long tid = (long long)blockIdx.x * blockDim.x + threadIdx.x;  // E*10
    if (tid >= (long long)EE * 10) return;
    int e = (int)(tid / 10), c = (int)(tid - (long long)e * 10);
    int s = g_src[e], d = g_dst[e];
    float nrm = g_norm[e];
    float4 v = ((const float4*)g_xw)[s * 10 + c];
    v.x *= nrm; v.y *= nrm; v.z *= nrm; v.w *= nrm;
    red_add_v4(g_oacc + d * CC + c * 4, v);
}

// ---------------- row finalize: bias, softmax, log_softmax, norms --------
__global__ void k_rowfinal(const float* __restrict__ b2, float* __restrict__ out) {
    int warp = threadIdx.x >> 5, lane = threadIdx.x & 31;
    int row = blockIdx.x * 8 + warp;
    if (row >= NN) return;
    const float NEG = -1e30f;
    float v0 = NEG, v1 = NEG;
    if (lane < CC)      v0 = g_oacc[row * CC + lane] + b2[lane];
    if (lane < CC - 32) v1 = g_oacc[row * CC + 32 + lane] + b2[32 + lane];
    float m = fmaxf(v0, v1);
    #pragma unroll
    for (int o = 16; o > 0; o >>= 1) m = fmaxf(m, __shfl_xor_sync(0xffffffffu, m, o));
    float e0 = (lane < CC)      ? __expf(v0 - m) : 0.f;
    float e1 = (lane < CC - 32) ? __expf(v1 - m) : 0.f;
    float s  = e0 + e1;
    float ss = (lane < CC ? v0 * v0 : 0.f) + (lane < CC - 32 ? v1 * v1 : 0.f);
    #pragma unroll
    for (int o = 16; o > 0; o >>= 1) {
        s  += __shfl_xor_sync(0xffffffffu, s, o);
        ss += __shfl_xor_sync(0xffffffffu, ss, o);
    }
    float lse = m + logf(s);
    float inv_s = 1.0f / s;
    if (lane == 0) g_rn[row] = 1.0f / fmaxf(sqrtf(ss), 1e-8f);
    if (lane < CC) {
        int idx = row * CC + lane;
        g_oacc[idx]          = v0;          // x_out kept for edge kernel
        out[OFF_LOGSM + idx] = v0 - lse;
        out[OFF_XOUT + idx]  = v0;
        out[OFF_SM + idx]    = e0 * inv_s;
    }
    if (lane < CC - 32) {
        int idx = row * CC + 32 + lane;
        g_oacc[idx]          = v1;
        out[OFF_LOGSM + idx] = v1 - lse;
        out[OFF_XOUT + idx]  = v1;
        out[OFF_SM + idx]    = e1 * inv_s;
    }
}

// ---------------- per-edge cosine dissimilarity + gnn_edge ----------------
__global__ void k_edge(const float* __restrict__ ew, float* __restrict__ out) {
    int e = blockIdx.x * blockDim.x + threadIdx.x;
    if (e >= EE) return;
    int s = g_src[e], d = g_dst[e];
    const float4* A = (const float4*)g_oacc;
    float dot = 0.f;
    #pragma unroll
    for (int j = 0; j < 10; j++) {
        float4 a = A[s * 10 + j];
        float4 b = A[d * 10 + j];
        dot += a.x * b.x + a.y * b.y + a.z * b.z + a.w * b.w;
    }
    out[OFF_COS + e] = 1.0f - dot * g_rn[s] * g_rn[d];
    out[OFF_GNN + e] = (ew[e] > 0.5f) ? 1.0f : -1.0f;
}

// ---------------- launch ----------------
extern "C" void kernel_launch(void* const* d_in, const int* in_sizes, int n_in,
                              void* d_out, int out_size) {
    const float* x   = (const float*)d_in[0];
    const void*  ei  = d_in[1];
    const float* ew  = (const float*)d_in[2];
    const float* W1  = (const float*)d_in[3];
    const float* b1  = (const float*)d_in[4];
    const float* W2  = (const float*)d_in[5];
    const float* b2  = (const float*)d_in[6];
    float* out = (float*)d_out;

    const int TB = 256;

    k_detect<<<1, 32>>>((const unsigned*)ei);
    k_convert<<<(EE + TB - 1) / TB, TB>>>(ei);
    k_deg_init<<<(NN + TB - 1) / TB, TB>>>();
    k_deg_acc<<<(EE + TB - 1) / TB, TB>>>();
    k_dinv<<<(NN + TB - 1) / TB, TB>>>();
    k_norm<<<(EE + TB - 1) / TB, TB>>>();

    k_gemm1<<<(NN + 63) / 64, 256>>>(x, W1);
    k_init1<<<(NN * 16 + TB - 1) / TB, TB>>>();
    k_scatter1<<<(EE * 16 + TB - 1) / TB, TB>>>();
    k_relu<<<(NN * 16 + TB - 1) / TB, TB>>>(b1);

    k_gemm2<<<(NN * CC + 255) / 256, 256>>>(W2);
    k_init2<<<(NN * 10 + TB - 1) / TB, TB>>>();
    k_scatter2<<<(EE * 10 + TB - 1) / TB, TB>>>();

    k_rowfinal<<<(NN + 7) / 8, 256>>>(b2, out);
    k_edge<<<(EE + TB - 1) / TB, TB>>>(ew, out);
}